// round 13
// baseline (speedup 1.0000x reference)
#include <cuda_runtime.h>
#include <math.h>
#include <stdint.h>

#define BB 8
#define NN 1024
#define DD 512
#define HH 8
#define HD 64

__device__ float g_qT[BB*HH*HD*NN];    // [B,H,d,n]   16MB (tf32-rounded)
__device__ float g_kT[BB*HH*HD*NN];    // [B,H,d,n]   16MB (tf32-rounded)
__device__ float g_v [BB*HH*NN*HD];    // [B,H,n,d]   16MB (tf32-rounded)
__device__ float g_y [BB*NN*DD];       // [token, D]  16MB (tf32-rounded)
__device__ float g_x [BB*NN*DD];       // pre-rounded x      16MB
__device__ float g_wq[DD*3*DD];        // pre-rounded W_qkv   3MB
__device__ float g_wo[DD*DD];          // pre-rounded W_o     1MB
__device__ float g_biasT[(size_t)BB*HH*NN*NN];  // [B,H,q,k] 268MB

__device__ __forceinline__ float cvt_tf32(float x) {
    uint32_t u;
    asm("cvt.rna.tf32.f32 %0, %1;" : "=r"(u) : "f"(x));
    return __uint_as_float(u);
}

#define MMA16N8K8(d, a0, a1, a2, a3, b0, b1)                              \
    asm volatile("mma.sync.aligned.m16n8k8.row.col.f32.tf32.tf32.f32 "    \
                 "{%0,%1,%2,%3},{%4,%5,%6,%7},{%8,%9},{%0,%1,%2,%3};"     \
                 : "+f"(d[0]), "+f"(d[1]), "+f"(d[2]), "+f"(d[3])         \
                 : "r"(a0), "r"(a1), "r"(a2), "r"(a3), "r"(b0), "r"(b1))

#define CP16(dst, src) \
    asm volatile("cp.async.cg.shared.global [%0], [%1], 16;" :: "r"(dst), "l"(src))
#define CP_COMMIT() asm volatile("cp.async.commit_group;")
#define CP_WAIT1()  asm volatile("cp.async.wait_group 1;")
#define CP_WAIT0()  asm volatile("cp.async.wait_group 0;")

// ---------------------------------------------------------------------------
// K-pre: elementwise tf32 rounding (float4 vectorized)
// ---------------------------------------------------------------------------
__global__ __launch_bounds__(256) void hp_cvt4(const float4* __restrict__ in,
                                               float4* __restrict__ out)
{
    const size_t i = (size_t)blockIdx.x * 256 + threadIdx.x;
    float4 t = in[i];
    t.x = cvt_tf32(t.x); t.y = cvt_tf32(t.y);
    t.z = cvt_tf32(t.z); t.w = cvt_tf32(t.w);
    out[i] = t;
}

// ---------------------------------------------------------------------------
// K0: bias transpose  [B][q][k][H] -> g_biasT [B][H][q*k]
// Persistent grid-stride (592 CTAs) — R8 configuration.
// ---------------------------------------------------------------------------
__global__ __launch_bounds__(256) void hp_bias_T(const float* __restrict__ bias)
{
    const size_t total  = (size_t)BB * 1048576;
    const size_t stride = (size_t)gridDim.x * 256;
    for (size_t idx = (size_t)blockIdx.x * 256 + threadIdx.x;
         idx < total; idx += stride) {
        const int    b  = (int)(idx >> 20);
        const size_t qk = idx & 1048575;
        const float4* p = (const float4*)(bias + (idx << 3));
        float4 t0 = p[0];
        float4 t1 = p[1];
        float* o = g_biasT + (size_t)b * 8388608 + qk;
        o[0 * 1048576] = t0.x; o[1 * 1048576] = t0.y;
        o[2 * 1048576] = t0.z; o[3 * 1048576] = t0.w;
        o[4 * 1048576] = t1.x; o[5 * 1048576] = t1.y;
        o[6 * 1048576] = t1.z; o[7 * 1048576] = t1.w;
    }
}

// ---------------------------------------------------------------------------
// K1/K3: tf32 HMMA GEMM, BM=128, BN=128, BK=32, cp.async triple-buffered.
// SPLIT=true epilogue now stages the 128x128 tile in smem and writes q/k/v
// with fully-coalesced float4 stores (fixes 12.5-25% sector efficiency).
// ---------------------------------------------------------------------------
template<int LDN, bool SPLIT>
__global__ __launch_bounds__(256, 2) void hp_gemm_mma(
    const float* __restrict__ A, const float* __restrict__ Wm,
    const float* __restrict__ bv, float* __restrict__ outp)
{
    extern __shared__ float sm[];
    float* As = sm;                 // [3][128*36]
    float* Bs = sm + 3 * 128 * 36;  // [3][32*136]

    const int tid  = threadIdx.x;
    const int warp = tid >> 5, lane = tid & 31;
    const int grp  = lane >> 2, tg = lane & 3;
    const int wm   = warp >> 1, wn = warp & 1;
    const int bm   = blockIdx.y * 128, bn = blockIdx.x * 128;

    const uint32_t sA = (uint32_t)__cvta_generic_to_shared(As);
    const uint32_t sB = (uint32_t)__cvta_generic_to_shared(Bs);

    float acc[2][8][4];
#pragma unroll
    for (int i = 0; i < 2; ++i)
#pragma unroll
        for (int j = 0; j < 8; ++j)
#pragma unroll
            for (int r = 0; r < 4; ++r) acc[i][j][r] = 0.f;

    auto load_tile = [&](int k0, int buf) {
#pragma unroll
        for (int i = 0; i < 4; ++i) {
            int v = i * 256 + tid;
            int r = v >> 3, c4 = (v & 7) << 2;
            CP16(sA + (buf * 128 * 36 + r * 36 + c4) * 4,
                 &A[(size_t)(bm + r) * 512 + k0 + c4]);
        }
#pragma unroll
        for (int i = 0; i < 4; ++i) {
            int v = i * 256 + tid;
            int r = v >> 5, c4 = (v & 31) << 2;
            CP16(sB + (buf * 32 * 136 + r * 136 + c4) * 4,
                 &Wm[(size_t)(k0 + r) * LDN + bn + c4]);
        }
    };

    load_tile(0, 0);  CP_COMMIT();
    load_tile(32, 1); CP_COMMIT();

    int buf_cur = 0, buf_next2 = 2;
    for (int it = 0; it < 16; ++it) {
        if (it < 15) { CP_WAIT1(); } else { CP_WAIT0(); }
        __syncthreads();
        if (it + 2 < 16) {
            load_tile((it + 2) * 32, buf_next2);
            CP_COMMIT();
        }

        const float* Ac = As + buf_cur * 128 * 36;
        const float* Bc = Bs + buf_cur * 32 * 136;
#pragma unroll
        for (int ks = 0; ks < 4; ++ks) {
            const int kb = ks * 8;
            uint32_t a[2][4];
#pragma unroll
            for (int mf = 0; mf < 2; ++mf) {
                int r = wm * 32 + mf * 16 + grp;
                a[mf][0] = __float_as_uint(Ac[r * 36 + kb + tg]);
                a[mf][1] = __float_as_uint(Ac[(r + 8) * 36 + kb + tg]);
                a[mf][2] = __float_as_uint(Ac[r * 36 + kb + tg + 4]);
                a[mf][3] = __float_as_uint(Ac[(r + 8) * 36 + kb + tg + 4]);
            }
#pragma unroll
            for (int nf = 0; nf < 8; ++nf) {
                int c = wn * 64 + nf * 8 + grp;
                uint32_t b0 = __float_as_uint(Bc[(kb + tg) * 136 + c]);
                uint32_t b1 = __float_as_uint(Bc[(kb + tg + 4) * 136 + c]);
                MMA16N8K8(acc[0][nf], a[0][0], a[0][1], a[0][2], a[0][3], b0, b1);
                MMA16N8K8(acc[1][nf], a[1][0], a[1][1], a[1][2], a[1][3], b0, b1);
            }
        }
        buf_cur   = (buf_cur   == 2) ? 0 : buf_cur + 1;
        buf_next2 = (buf_next2 == 2) ? 0 : buf_next2 + 1;
    }

    if (!SPLIT) {
        // direct coalesced write (out matrix is row-major, already fine)
#pragma unroll
        for (int mf = 0; mf < 2; ++mf) {
#pragma unroll
            for (int rr = 0; rr < 2; ++rr) {
                const int m = bm + wm * 32 + mf * 16 + grp + rr * 8;
#pragma unroll
                for (int nf = 0; nf < 8; ++nf) {
                    const int c = bn + wn * 64 + nf * 8 + tg * 2;
                    float2 w2 = make_float2(acc[mf][nf][rr * 2]     + bv[c],
                                            acc[mf][nf][rr * 2 + 1] + bv[c + 1]);
                    *(float2*)&outp[(size_t)m * 512 + c] = w2;
                }
            }
        }
        return;
    }

    // ---- SPLIT epilogue: stage in smem, write coalesced ----
    __syncthreads();   // main-loop buffers dead; reuse sm
    // two 64-col segments; q/k staged [c][132], v staged [m][68]
    const int wh0 = ((bn)      >> 6) % 3;
    const int wh1 = ((bn + 64) >> 6) % 3;

#pragma unroll
    for (int mf = 0; mf < 2; ++mf) {
#pragma unroll
        for (int rr = 0; rr < 2; ++rr) {
            const int m_l = wm * 32 + mf * 16 + grp + rr * 8;
#pragma unroll
            for (int nf = 0; nf < 8; ++nf) {
                const int c_l = wn * 64 + nf * 8 + tg * 2;
                float v0 = cvt_tf32(acc[mf][nf][rr * 2]     + bv[bn + c_l]);
                float v1 = cvt_tf32(acc[mf][nf][rr * 2 + 1] + bv[bn + c_l + 1]);
                const int seg = c_l >> 6, cs = c_l & 63;
                const int wh  = seg ? wh1 : wh0;
                float* Es = sm + seg * 8704;
                if (wh == 2) {
                    Es[m_l * 68 + cs]     = v0;
                    Es[m_l * 68 + cs + 1] = v1;
                } else {
                    Es[cs * 132 + m_l]       = v0;
                    Es[(cs + 1) * 132 + m_l] = v1;
                }
            }
        }
    }
    __syncthreads();

    const int bi = bm >> 10, n0g = bm & 1023;
#pragma unroll
    for (int seg = 0; seg < 2; ++seg) {
        const int csg = bn + seg * 64;
        const int h   = csg / 192;
        const int wh  = (csg >> 6) % 3;
        const float* Es = sm + seg * 8704;
        if (wh == 2) {
            const int m = tid >> 1, t0 = (tid & 1) * 32;
            float* dst = g_v + (((size_t)(bi * 8 + h) * 1024) + n0g + m) * 64 + t0;
#pragma unroll
            for (int j = 0; j < 8; ++j)
                *(float4*)&dst[j * 4] = *(const float4*)&Es[m * 68 + t0 + j * 4];
        } else {
            float* P = (wh == 0) ? g_qT : g_kT;
            const int c2 = tid >> 2, m0 = (tid & 3) * 32;
            float* dst = P + (((size_t)(bi * 8 + h) * 64 + c2) * 1024) + n0g + m0;
#pragma unroll
            for (int j = 0; j < 8; ++j)
                *(float4*)&dst[j * 4] = *(const float4*)&Es[c2 * 132 + m0 + j * 4];
        }
        __syncthreads();
    }
}

// ---------------------------------------------------------------------------
// K2: flash attention — EXACT R8 version (best measured).
// ---------------------------------------------------------------------------
__global__ __launch_bounds__(256, 2) void hp_attn_mma()
{
    extern __shared__ float sm[];
    float* Ks = sm;                      // 2*64*40  = 5120
    float* Vs = sm + 5120;               // 2*32*72  = 4608
    float* Bb = sm + 9728;               // 2*128*40 = 10240
    float* Ps = sm + 19968;              // 128*36   = 4608

    const int tid  = threadIdx.x;
    const int warp = tid >> 5, lane = tid & 31;
    const int grp  = lane >> 2, tg = lane & 3;
    const int h  = blockIdx.x;
    const int qt = blockIdx.y;
    const int b  = blockIdx.z;
    const int bh = b * HH + h;
    const int q0 = qt * 128;

    const uint32_t sK = (uint32_t)__cvta_generic_to_shared(Ks);
    const uint32_t sV = (uint32_t)__cvta_generic_to_shared(Vs);
    const uint32_t sBb = (uint32_t)__cvta_generic_to_shared(Bb);

    const float* kb = g_kT + (size_t)bh * HD * NN;
    const float* vb = g_v  + (size_t)bh * NN * HD;
    const float* bias_bh = g_biasT + ((size_t)bh << 20);

    auto load_tile = [&](int k0, int buf) {
#pragma unroll
        for (int i = 0; i < 2; ++i) {                 // Ks: 64 x 32
            int v = i * 256 + tid;
            int d = v >> 3, c4 = (v & 7) << 2;
            CP16(sK + (buf * 2560 + d * 40 + c4) * 4,
                 &kb[(size_t)d * NN + k0 + c4]);
        }
#pragma unroll
        for (int i = 0; i < 2; ++i) {                 // Vs: 32 x 64
            int v = i * 256 + tid;
            int r = v >> 4, c4 = (v & 15) << 2;
            CP16(sV + (buf * 2304 + r * 72 + c4) * 4,
                 &vb[(size_t)(k0 + r) * HD + c4]);
        }
#pragma unroll
        for (int i = 0; i < 4; ++i) {                 // Bb: 128 x 32
            int v = i * 256 + tid;
            int r = v >> 3, c4 = (v & 7) << 2;
            CP16(sBb + (buf * 5120 + r * 40 + c4) * 4,
                 &bias_bh[(size_t)(q0 + r) * 1024 + k0 + c4]);
        }
    };

    load_tile(0, 0);
    CP_COMMIT();

    const float* qbase = g_qT + (size_t)bh * HD * NN;
    const int qr = q0 + warp * 16 + grp;
    uint32_t qa[8][4];
#pragma unroll
    for (int s = 0; s < 8; ++s) {
        int d0 = s * 8 + tg;
        qa[s][0] = __float_as_uint(qbase[(size_t)d0       * NN + qr]     * 0.125f);
        qa[s][1] = __float_as_uint(qbase[(size_t)d0       * NN + qr + 8] * 0.125f);
        qa[s][2] = __float_as_uint(qbase[(size_t)(d0 + 4) * NN + qr]     * 0.125f);
        qa[s][3] = __float_as_uint(qbase[(size_t)(d0 + 4) * NN + qr + 8] * 0.125f);
    }

    float o[8][4];
#pragma unroll
    for (int i = 0; i < 8; ++i)
#pragma unroll
        for (int j = 0; j < 4; ++j) o[i][j] = 0.f;
    float m0 = -1e30f, m1 = -1e30f, l0 = 0.f, l1 = 0.f;

    const int r0 = warp * 16 + grp;

    for (int kt = 0; kt < 32; ++kt) {
        const int cur = kt & 1;
        if (kt < 31) {
            load_tile((kt + 1) * 32, cur ^ 1);
            CP_COMMIT();
            CP_WAIT1();
        } else {
            CP_WAIT0();
        }
        __syncthreads();

        const float* Kc = Ks + cur * 2560;
        const float* Vc = Vs + cur * 2304;
        const float* Bc = Bb + cur * 5120;

        float s_[4][4];
#pragma unroll
        for (int nf = 0; nf < 4; ++nf)
#pragma unroll
            for (int r = 0; r < 4; ++r) s_[nf][r] = 0.f;
#pragma unroll
        for (int ks = 0; ks < 8; ++ks) {
#pragma unroll
            for (int nf = 0; nf < 4; ++nf) {
                int key = nf * 8 + grp;
                uint32_t b0 = __float_as_uint(Kc[(ks * 8 + tg) * 40 + key]);
                uint32_t b1 = __float_as_uint(Kc[(ks * 8 + tg + 4) * 40 + key]);
                MMA16N8K8(s_[nf], qa[ks][0], qa[ks][1], qa[ks][2], qa[ks][3], b0, b1);
            }
        }
#pragma unroll
        for (int nf = 0; nf < 4; ++nf) {
            int c = nf * 8 + tg * 2;
            float2 t0 = *(const float2*)&Bc[r0 * 40 + c];
            float2 t1 = *(const float2*)&Bc[(r0 + 8) * 40 + c];
            s_[nf][0] += t0.x; s_[nf][1] += t0.y;
            s_[nf][2] += t1.x; s_[nf][3] += t1.y;
        }

        float mx0 = -1e30f, mx1 = -1e30f;
#pragma unroll
        for (int nf = 0; nf < 4; ++nf) {
            mx0 = fmaxf(mx0, fmaxf(s_[nf][0], s_[nf][1]));
            mx1 = fmaxf(mx1, fmaxf(s_[nf][2], s_[nf][3]));
        }
        mx0 = fmaxf(mx0, __shfl_xor_sync(0xffffffffu, mx0, 1));
        mx0 = fmaxf(mx0, __shfl_xor_sync(0xffffffffu, mx0, 2));
        mx1 = fmaxf(mx1, __shfl_xor_sync(0xffffffffu, mx1, 1));
        mx1 = fmaxf(mx1, __shfl_xor_sync(0xffffffffu, mx1, 2));
        float mn0 = fmaxf(m0, mx0), mn1 = fmaxf(m1, mx1);
        float sc0 = __expf(m0 - mn0), sc1 = __expf(m1 - mn1);
        float sum0 = 0.f, sum1 = 0.f;
#pragma unroll
        for (int nf = 0; nf < 4; ++nf) {
            s_[nf][0] = __expf(s_[nf][0] - mn0);
            s_[nf][1] = __expf(s_[nf][1] - mn0);
            s_[nf][2] = __expf(s_[nf][2] - mn1);
            s_[nf][3] = __expf(s_[nf][3] - mn1);
            sum0 += s_[nf][0] + s_[nf][1];
            sum1 += s_[nf][2] + s_[nf][3];
        }
        sum0 += __shfl_xor_sync(0xffffffffu, sum0, 1);
        sum0 += __shfl_xor_sync(0xffffffffu, sum0, 2);
        sum1 += __shfl_xor_sync(0xffffffffu, sum1, 1);
        sum1 += __shfl_xor_sync(0xffffffffu, sum1, 2);
        l0 = l0 * sc0 + sum0;
        l1 = l1 * sc1 + sum1;
        m0 = mn0; m1 = mn1;

#pragma unroll
        for (int nf = 0; nf < 8; ++nf) {
            o[nf][0] *= sc0; o[nf][1] *= sc0;
            o[nf][2] *= sc1; o[nf][3] *= sc1;
        }

#pragma unroll
        for (int nf = 0; nf < 4; ++nf) {
            int c = nf * 8 + tg * 2;
            float2 p0 = make_float2(cvt_tf32(s_[nf][0]), cvt_tf32(s_[nf][1]));
            float2 p1 = make_float2(cvt_tf32(s_[nf][2]), cvt_tf32(s_[nf][3]));
            *(float2*)&Ps[r0 * 36 + c]       = p0;
            *(float2*)&Ps[(r0 + 8) * 36 + c] = p1;
        }
        __syncwarp();

#pragma unroll
        for (int ks = 0; ks < 4; ++ks) {
            uint32_t a0 = __float_as_uint(Ps[r0 * 36 + ks * 8 + tg]);
            uint32_t a1 = __float_as_uint(Ps[(r0 + 8) * 36 + ks * 8 + tg]);
            uint32_t a2 = __float_as_uint(Ps[r0 * 36 + ks * 8 + tg + 4]);
            uint32_t a3 = __float_as_uint(Ps[(r0 + 8) * 36 + ks * 8 + tg + 4]);
#pragma unroll
            for (int nf = 0; nf < 8; ++nf) {
                int dc = nf * 8 + grp;
                uint32_t b0 = __float_as_uint(Vc[(ks * 8 + tg) * 72 + dc]);
                uint32_t b1 = __float_as_uint(Vc[(ks * 8 + tg + 4) * 72 + dc]);
                MMA16N8K8(o[nf], a0, a1, a2, a3, b0, b1);
            }
        }
        __syncthreads();
    }

    const float inv0 = 1.f / l0, inv1 = 1.f / l1;
    const size_t row0 = (size_t)b * NN + q0 + warp * 16 + grp;
    const size_t row1 = row0 + 8;
#pragma unroll
    for (int nf = 0; nf < 8; ++nf) {
        int c = h * 64 + nf * 8 + tg * 2;
        float2 w0 = make_float2(cvt_tf32(o[nf][0] * inv0), cvt_tf32(o[nf][1] * inv0));
        float2 w1 = make_float2(cvt_tf32(o[nf][2] * inv1), cvt_tf32(o[nf][3] * inv1));
        *(float2*)&g_y[row0 * DD + c] = w0;
        *(float2*)&g_y[row1 * DD + c] = w1;
    }
}

// ---------------------------------------------------------------------------
extern "C" void kernel_launch(void* const* d_in, const int* in_sizes, int n_in,
                              void* d_out, int out_size)
{
    const float* x    = (const float*)d_in[0];
    const float* bias = (const float*)d_in[1];
    const float* Wqkv = (const float*)d_in[2];
    const float* bqkv = (const float*)d_in[3];
    const float* Wo   = (const float*)d_in[4];
    const float* bo   = (const float*)d_in[5];
    float* out = (float*)d_out;

    const int gemm_smem = (3 * 128 * 36 + 3 * 32 * 136) * 4;  // 107520
    const int attn_smem = 24576 * 4;                          // 98304

    cudaFuncSetAttribute(hp_gemm_mma<1536, true>,
                         cudaFuncAttributeMaxDynamicSharedMemorySize, gemm_smem);
    cudaFuncSetAttribute(hp_gemm_mma<512, false>,
                         cudaFuncAttributeMaxDynamicSharedMemorySize, gemm_smem);
    cudaFuncSetAttribute(hp_attn_mma,
                         cudaFuncAttributeMaxDynamicSharedMemorySize, attn_smem);

    float* gx;  cudaGetSymbolAddress((void**)&gx,  g_x);
    float* gwq; cudaGetSymbolAddress((void**)&gwq, g_wq);
    float* gwo; cudaGetSymbolAddress((void**)&gwo, g_wo);
    float* gy;  cudaGetSymbolAddress((void**)&gy,  g_y);

    // Fork (R8 config): persistent bias transpose on side stream.
    cudaStream_t s1;
    cudaStreamCreateWithFlags(&s1, cudaStreamNonBlocking);
    cudaEvent_t eFork, eJoin;
    cudaEventCreateWithFlags(&eFork, cudaEventDisableTiming);
    cudaEventCreateWithFlags(&eJoin, cudaEventDisableTiming);

    cudaEventRecord(eFork, 0);
    cudaStreamWaitEvent(s1, eFork, 0);
    hp_bias_T<<<592, 256, 0, s1>>>(bias);
    cudaEventRecord(eJoin, s1);

    hp_cvt4<<<BB*NN*DD/4/256, 256>>>((const float4*)x,    (float4*)gx);
    hp_cvt4<<<DD*3*DD/4/256, 256>>>((const float4*)Wqkv, (float4*)gwq);
    hp_cvt4<<<DD*DD/4/256,   256>>>((const float4*)Wo,   (float4*)gwo);
    hp_gemm_mma<1536, true ><<<dim3(12, 64), 256, gemm_smem>>>(gx, gwq, bqkv, nullptr);

    cudaStreamWaitEvent(0, eJoin, 0);
    hp_attn_mma<<<dim3(HH, NN / 128, BB), 256, attn_smem>>>();
    hp_gemm_mma<512, false><<<dim3(4, 64), 256, gemm_smem>>>(gy, gwo, bo, out);

    cudaEventDestroy(eFork);
    cudaEventDestroy(eJoin);
    cudaStreamDestroy(s1);
}

// round 14
// speedup vs baseline: 1.0408x; 1.0408x over previous
#include <cuda_runtime.h>
#include <math.h>
#include <stdint.h>

#define BB 8
#define NN 1024
#define DD 512
#define HH 8
#define HD 64

__device__ float g_qT[BB*HH*HD*NN];    // [B,H,d,n]   16MB (tf32-rounded)
__device__ float g_kT[BB*HH*HD*NN];    // [B,H,d,n]   16MB (tf32-rounded)
__device__ float g_v [BB*HH*NN*HD];    // [B,H,n,d]   16MB (tf32-rounded)
__device__ float g_y [BB*NN*DD];       // [token, D]  16MB (tf32-rounded)
__device__ float g_x [BB*NN*DD];       // pre-rounded x        16MB
__device__ float g_wqT[3*DD*DD];       // W_qkv^T [1536][512]   3MB (rounded)
__device__ float g_woT[DD*DD];         // W_o^T   [512][512]    1MB (rounded)
__device__ float g_biasT[(size_t)BB*HH*NN*NN];  // [B,H,q,k] 268MB

__device__ __forceinline__ float cvt_tf32(float x) {
    uint32_t u;
    asm("cvt.rna.tf32.f32 %0, %1;" : "=r"(u) : "f"(x));
    return __uint_as_float(u);
}

#define MMA16N8K8(d, a0, a1, a2, a3, b0, b1)                              \
    asm volatile("mma.sync.aligned.m16n8k8.row.col.f32.tf32.tf32.f32 "    \
                 "{%0,%1,%2,%3},{%4,%5,%6,%7},{%8,%9},{%0,%1,%2,%3};"     \
                 : "+f"(d[0]), "+f"(d[1]), "+f"(d[2]), "+f"(d[3])         \
                 : "r"(a0), "r"(a1), "r"(a2), "r"(a3), "r"(b0), "r"(b1))

#define LDSM_X4(r0, r1, r2, r3, addr)                                     \
    asm volatile("ldmatrix.sync.aligned.m8n8.x4.shared.b16 "              \
                 "{%0,%1,%2,%3}, [%4];"                                   \
                 : "=r"(r0), "=r"(r1), "=r"(r2), "=r"(r3) : "r"(addr))

#define CP16(dst, src) \
    asm volatile("cp.async.cg.shared.global [%0], [%1], 16;" :: "r"(dst), "l"(src))
#define CP_COMMIT() asm volatile("cp.async.commit_group;")
#define CP_WAIT1()  asm volatile("cp.async.wait_group 1;")
#define CP_WAIT0()  asm volatile("cp.async.wait_group 0;")

// ---------------------------------------------------------------------------
// K-pre: elementwise tf32 rounding (x)
// ---------------------------------------------------------------------------
__global__ __launch_bounds__(256) void hp_cvt4(const float4* __restrict__ in,
                                               float4* __restrict__ out)
{
    const size_t i = (size_t)blockIdx.x * 256 + threadIdx.x;
    float4 t = in[i];
    t.x = cvt_tf32(t.x); t.y = cvt_tf32(t.y);
    t.z = cvt_tf32(t.z); t.w = cvt_tf32(t.w);
    out[i] = t;
}

// ---------------------------------------------------------------------------
// K-pre: weight transpose + round: in[K][N] -> out[N][K]
// ---------------------------------------------------------------------------
__global__ void hp_wT(const float* __restrict__ in, float* __restrict__ out,
                      int K, int N)
{
    __shared__ float t[32][33];
    const int n0 = blockIdx.x * 32, k0 = blockIdx.y * 32;
    const int tx = threadIdx.x, ty = threadIdx.y;
#pragma unroll
    for (int i = 0; i < 4; ++i)
        t[ty + i * 8][tx] = cvt_tf32(in[(size_t)(k0 + ty + i * 8) * N + n0 + tx]);
    __syncthreads();
#pragma unroll
    for (int i = 0; i < 4; ++i)
        out[(size_t)(n0 + ty + i * 8) * K + k0 + tx] = t[tx][ty + i * 8];
}

// ---------------------------------------------------------------------------
// K0: bias transpose  [B][q][k][H] -> g_biasT [B][H][q*k]
// ---------------------------------------------------------------------------
__global__ __launch_bounds__(256) void hp_bias_T(const float* __restrict__ bias)
{
    const size_t total  = (size_t)BB * 1048576;
    const size_t stride = (size_t)gridDim.x * 256;
    for (size_t idx = (size_t)blockIdx.x * 256 + threadIdx.x;
         idx < total; idx += stride) {
        const int    b  = (int)(idx >> 20);
        const size_t qk = idx & 1048575;
        const float4* p = (const float4*)(bias + (idx << 3));
        float4 t0 = p[0];
        float4 t1 = p[1];
        float* o = g_biasT + (size_t)b * 8388608 + qk;
        o[0 * 1048576] = t0.x; o[1 * 1048576] = t0.y;
        o[2 * 1048576] = t0.z; o[3 * 1048576] = t0.w;
        o[4 * 1048576] = t1.x; o[5 * 1048576] = t1.y;
        o[6 * 1048576] = t1.z; o[7 * 1048576] = t1.w;
    }
}

// ---------------------------------------------------------------------------
// K1/K3: tf32 HMMA GEMM, BM=128, BN=128, BK=32, triple-buffered cp.async.
// Fragment loads via ldmatrix.x4 (A [m][k] tile; B tile stored [n][k] from
// pre-transposed weights) — 24 LDSM/tile instead of 96 scalar LDS.
// ---------------------------------------------------------------------------
template<bool SPLIT>
__global__ __launch_bounds__(256, 2) void hp_gemm_mma(
    const float* __restrict__ A, const float* __restrict__ WT,
    const float* __restrict__ bv, float* __restrict__ outp)
{
    extern __shared__ float sm[];
    float* As = sm;                 // [3][128*36]  ([m][k], stride 36)
    float* Bs = sm + 3 * 4608;      // [3][128*36]  ([n][k], stride 36)

    const int tid  = threadIdx.x;
    const int warp = tid >> 5, lane = tid & 31;
    const int grp  = lane >> 2, tg = lane & 3;
    const int wm   = warp >> 1, wn = warp & 1;
    const int bm   = blockIdx.y * 128, bn = blockIdx.x * 128;

    const uint32_t sA = (uint32_t)__cvta_generic_to_shared(As);
    const uint32_t sB = (uint32_t)__cvta_generic_to_shared(Bs);

    float acc[2][8][4];
#pragma unroll
    for (int i = 0; i < 2; ++i)
#pragma unroll
        for (int j = 0; j < 8; ++j)
#pragma unroll
            for (int r = 0; r < 4; ++r) acc[i][j][r] = 0.f;

    auto load_tile = [&](int k0, int buf) {
#pragma unroll
        for (int i = 0; i < 4; ++i) {
            int v = i * 256 + tid;
            int r = v >> 3, c4 = (v & 7) << 2;
            CP16(sA + (buf * 4608 + r * 36 + c4) * 4,
                 &A[(size_t)(bm + r) * 512 + k0 + c4]);
        }
#pragma unroll
        for (int i = 0; i < 4; ++i) {
            int v = i * 256 + tid;
            int r = v >> 3, c4 = (v & 7) << 2;
            CP16(sB + (buf * 4608 + r * 36 + c4) * 4,
                 &WT[(size_t)(bn + r) * 512 + k0 + c4]);
        }
    };

    load_tile(0, 0);  CP_COMMIT();
    load_tile(32, 1); CP_COMMIT();

    // per-thread ldmatrix address offsets (within a buffer), in bytes
    const uint32_t aOff = (uint32_t)(((wm * 32 + (lane & 15)) * 36 +
                                      ((lane >> 4) << 2)) * 4);
    const uint32_t bOff = (uint32_t)(((wn * 64 + (lane & 7) +
                                       (((lane >> 4) & 1) << 3)) * 36 +
                                      (((lane >> 3) & 1) << 2)) * 4);

    int buf_cur = 0, buf_next2 = 2;
    for (int it = 0; it < 16; ++it) {
        if (it < 15) { CP_WAIT1(); } else { CP_WAIT0(); }
        __syncthreads();
        if (it + 2 < 16) {
            load_tile((it + 2) * 32, buf_next2);
            CP_COMMIT();
        }

        const uint32_t aBase = sA + buf_cur * 4608 * 4 + aOff;
        const uint32_t bBase = sB + buf_cur * 4608 * 4 + bOff;
#pragma unroll
        for (int ks = 0; ks < 4; ++ks) {
            uint32_t a0[4], a1[4];
            LDSM_X4(a0[0], a0[1], a0[2], a0[3], aBase + ks * 32);
            LDSM_X4(a1[0], a1[1], a1[2], a1[3], aBase + 16 * 144 + ks * 32);
#pragma unroll
            for (int nfp = 0; nfp < 4; ++nfp) {
                uint32_t b0, b1, b2, b3;
                LDSM_X4(b0, b1, b2, b3, bBase + nfp * 16 * 144 + ks * 32);
                MMA16N8K8(acc[0][nfp * 2],     a0[0], a0[1], a0[2], a0[3], b0, b1);
                MMA16N8K8(acc[1][nfp * 2],     a1[0], a1[1], a1[2], a1[3], b0, b1);
                MMA16N8K8(acc[0][nfp * 2 + 1], a0[0], a0[1], a0[2], a0[3], b2, b3);
                MMA16N8K8(acc[1][nfp * 2 + 1], a1[0], a1[1], a1[2], a1[3], b2, b3);
            }
        }
        buf_cur   = (buf_cur   == 2) ? 0 : buf_cur + 1;
        buf_next2 = (buf_next2 == 2) ? 0 : buf_next2 + 1;
    }

#pragma unroll
    for (int mf = 0; mf < 2; ++mf) {
#pragma unroll
        for (int rr = 0; rr < 2; ++rr) {
            const int m = bm + wm * 32 + mf * 16 + grp + rr * 8;
#pragma unroll
            for (int nf = 0; nf < 8; ++nf) {
                const int c = bn + wn * 64 + nf * 8 + tg * 2;
                float v0 = acc[mf][nf][rr * 2]     + bv[c];
                float v1 = acc[mf][nf][rr * 2 + 1] + bv[c + 1];
                if (SPLIT) {
                    v0 = cvt_tf32(v0);
                    v1 = cvt_tf32(v1);
                    int bi = m >> 10, n = m & 1023;
                    int h = c / 192, rem = c - h * 192;
                    int which = rem >> 6, t = rem & 63;
                    if (which == 0) {
                        g_qT[(((size_t)bi * 8 + h) * 64 + t)     * 1024 + n] = v0;
                        g_qT[(((size_t)bi * 8 + h) * 64 + t + 1) * 1024 + n] = v1;
                    } else if (which == 1) {
                        g_kT[(((size_t)bi * 8 + h) * 64 + t)     * 1024 + n] = v0;
                        g_kT[(((size_t)bi * 8 + h) * 64 + t + 1) * 1024 + n] = v1;
                    } else {
                        float2 w2 = make_float2(v0, v1);
                        *(float2*)&g_v[(((size_t)bi * 8 + h) * 1024 + n) * 64 + t] = w2;
                    }
                } else {
                    float2 w2 = make_float2(v0, v1);
                    *(float2*)&outp[(size_t)m * 512 + c] = w2;
                }
            }
        }
    }
}

// ---------------------------------------------------------------------------
// K2: flash attention — EXACT R8/R12 version (best measured).
// ---------------------------------------------------------------------------
__global__ __launch_bounds__(256, 2) void hp_attn_mma()
{
    extern __shared__ float sm[];
    float* Ks = sm;                      // 2*64*40  = 5120
    float* Vs = sm + 5120;               // 2*32*72  = 4608
    float* Bb = sm + 9728;               // 2*128*40 = 10240
    float* Ps = sm + 19968;              // 128*36   = 4608

    const int tid  = threadIdx.x;
    const int warp = tid >> 5, lane = tid & 31;
    const int grp  = lane >> 2, tg = lane & 3;
    const int h  = blockIdx.x;
    const int qt = blockIdx.y;
    const int b  = blockIdx.z;
    const int bh = b * HH + h;
    const int q0 = qt * 128;

    const uint32_t sK = (uint32_t)__cvta_generic_to_shared(Ks);
    const uint32_t sV = (uint32_t)__cvta_generic_to_shared(Vs);
    const uint32_t sBb = (uint32_t)__cvta_generic_to_shared(Bb);

    const float* kb = g_kT + (size_t)bh * HD * NN;
    const float* vb = g_v  + (size_t)bh * NN * HD;
    const float* bias_bh = g_biasT + ((size_t)bh << 20);

    auto load_tile = [&](int k0, int buf) {
#pragma unroll
        for (int i = 0; i < 2; ++i) {                 // Ks: 64 x 32
            int v = i * 256 + tid;
            int d = v >> 3, c4 = (v & 7) << 2;
            CP16(sK + (buf * 2560 + d * 40 + c4) * 4,
                 &kb[(size_t)d * NN + k0 + c4]);
        }
#pragma unroll
        for (int i = 0; i < 2; ++i) {                 // Vs: 32 x 64
            int v = i * 256 + tid;
            int r = v >> 4, c4 = (v & 15) << 2;
            CP16(sV + (buf * 2304 + r * 72 + c4) * 4,
                 &vb[(size_t)(k0 + r) * HD + c4]);
        }
#pragma unroll
        for (int i = 0; i < 4; ++i) {                 // Bb: 128 x 32
            int v = i * 256 + tid;
            int r = v >> 3, c4 = (v & 7) << 2;
            CP16(sBb + (buf * 5120 + r * 40 + c4) * 4,
                 &bias_bh[(size_t)(q0 + r) * 1024 + k0 + c4]);
        }
    };

    load_tile(0, 0);
    CP_COMMIT();

    const float* qbase = g_qT + (size_t)bh * HD * NN;
    const int qr = q0 + warp * 16 + grp;
    uint32_t qa[8][4];
#pragma unroll
    for (int s = 0; s < 8; ++s) {
        int d0 = s * 8 + tg;
        qa[s][0] = __float_as_uint(qbase[(size_t)d0       * NN + qr]     * 0.125f);
        qa[s][1] = __float_as_uint(qbase[(size_t)d0       * NN + qr + 8] * 0.125f);
        qa[s][2] = __float_as_uint(qbase[(size_t)(d0 + 4) * NN + qr]     * 0.125f);
        qa[s][3] = __float_as_uint(qbase[(size_t)(d0 + 4) * NN + qr + 8] * 0.125f);
    }

    float o[8][4];
#pragma unroll
    for (int i = 0; i < 8; ++i)
#pragma unroll
        for (int j = 0; j < 4; ++j) o[i][j] = 0.f;
    float m0 = -1e30f, m1 = -1e30f, l0 = 0.f, l1 = 0.f;

    const int r0 = warp * 16 + grp;

    for (int kt = 0; kt < 32; ++kt) {
        const int cur = kt & 1;
        if (kt < 31) {
            load_tile((kt + 1) * 32, cur ^ 1);
            CP_COMMIT();
            CP_WAIT1();
        } else {
            CP_WAIT0();
        }
        __syncthreads();

        const float* Kc = Ks + cur * 2560;
        const float* Vc = Vs + cur * 2304;
        const float* Bc = Bb + cur * 5120;

        float s_[4][4];
#pragma unroll
        for (int nf = 0; nf < 4; ++nf)
#pragma unroll
            for (int r = 0; r < 4; ++r) s_[nf][r] = 0.f;
#pragma unroll
        for (int ks = 0; ks < 8; ++ks) {
#pragma unroll
            for (int nf = 0; nf < 4; ++nf) {
                int key = nf * 8 + grp;
                uint32_t b0 = __float_as_uint(Kc[(ks * 8 + tg) * 40 + key]);
                uint32_t b1 = __float_as_uint(Kc[(ks * 8 + tg + 4) * 40 + key]);
                MMA16N8K8(s_[nf], qa[ks][0], qa[ks][1], qa[ks][2], qa[ks][3], b0, b1);
            }
        }
#pragma unroll
        for (int nf = 0; nf < 4; ++nf) {
            int c = nf * 8 + tg * 2;
            float2 t0 = *(const float2*)&Bc[r0 * 40 + c];
            float2 t1 = *(const float2*)&Bc[(r0 + 8) * 40 + c];
            s_[nf][0] += t0.x; s_[nf][1] += t0.y;
            s_[nf][2] += t1.x; s_[nf][3] += t1.y;
        }

        float mx0 = -1e30f, mx1 = -1e30f;
#pragma unroll
        for (int nf = 0; nf < 4; ++nf) {
            mx0 = fmaxf(mx0, fmaxf(s_[nf][0], s_[nf][1]));
            mx1 = fmaxf(mx1, fmaxf(s_[nf][2], s_[nf][3]));
        }
        mx0 = fmaxf(mx0, __shfl_xor_sync(0xffffffffu, mx0, 1));
        mx0 = fmaxf(mx0, __shfl_xor_sync(0xffffffffu, mx0, 2));
        mx1 = fmaxf(mx1, __shfl_xor_sync(0xffffffffu, mx1, 1));
        mx1 = fmaxf(mx1, __shfl_xor_sync(0xffffffffu, mx1, 2));
        float mn0 = fmaxf(m0, mx0), mn1 = fmaxf(m1, mx1);
        float sc0 = __expf(m0 - mn0), sc1 = __expf(m1 - mn1);
        float sum0 = 0.f, sum1 = 0.f;
#pragma unroll
        for (int nf = 0; nf < 4; ++nf) {
            s_[nf][0] = __expf(s_[nf][0] - mn0);
            s_[nf][1] = __expf(s_[nf][1] - mn0);
            s_[nf][2] = __expf(s_[nf][2] - mn1);
            s_[nf][3] = __expf(s_[nf][3] - mn1);
            sum0 += s_[nf][0] + s_[nf][1];
            sum1 += s_[nf][2] + s_[nf][3];
        }
        sum0 += __shfl_xor_sync(0xffffffffu, sum0, 1);
        sum0 += __shfl_xor_sync(0xffffffffu, sum0, 2);
        sum1 += __shfl_xor_sync(0xffffffffu, sum1, 1);
        sum1 += __shfl_xor_sync(0xffffffffu, sum1, 2);
        l0 = l0 * sc0 + sum0;
        l1 = l1 * sc1 + sum1;
        m0 = mn0; m1 = mn1;

#pragma unroll
        for (int nf = 0; nf < 8; ++nf) {
            o[nf][0] *= sc0; o[nf][1] *= sc0;
            o[nf][2] *= sc1; o[nf][3] *= sc1;
        }

#pragma unroll
        for (int nf = 0; nf < 4; ++nf) {
            int c = nf * 8 + tg * 2;
            float2 p0 = make_float2(cvt_tf32(s_[nf][0]), cvt_tf32(s_[nf][1]));
            float2 p1 = make_float2(cvt_tf32(s_[nf][2]), cvt_tf32(s_[nf][3]));
            *(float2*)&Ps[r0 * 36 + c]       = p0;
            *(float2*)&Ps[(r0 + 8) * 36 + c] = p1;
        }
        __syncwarp();

#pragma unroll
        for (int ks = 0; ks < 4; ++ks) {
            uint32_t a0 = __float_as_uint(Ps[r0 * 36 + ks * 8 + tg]);
            uint32_t a1 = __float_as_uint(Ps[(r0 + 8) * 36 + ks * 8 + tg]);
            uint32_t a2 = __float_as_uint(Ps[r0 * 36 + ks * 8 + tg + 4]);
            uint32_t a3 = __float_as_uint(Ps[(r0 + 8) * 36 + ks * 8 + tg + 4]);
#pragma unroll
            for (int nf = 0; nf < 8; ++nf) {
                int dc = nf * 8 + grp;
                uint32_t b0 = __float_as_uint(Vc[(ks * 8 + tg) * 72 + dc]);
                uint32_t b1 = __float_as_uint(Vc[(ks * 8 + tg + 4) * 72 + dc]);
                MMA16N8K8(o[nf], a0, a1, a2, a3, b0, b1);
            }
        }
        __syncthreads();
    }

    const float inv0 = 1.f / l0, inv1 = 1.f / l1;
    const size_t row0 = (size_t)b * NN + q0 + warp * 16 + grp;
    const size_t row1 = row0 + 8;
#pragma unroll
    for (int nf = 0; nf < 8; ++nf) {
        int c = h * 64 + nf * 8 + tg * 2;
        float2 w0 = make_float2(cvt_tf32(o[nf][0] * inv0), cvt_tf32(o[nf][1] * inv0));
        float2 w1 = make_float2(cvt_tf32(o[nf][2] * inv1), cvt_tf32(o[nf][3] * inv1));
        *(float2*)&g_y[row0 * DD + c] = w0;
        *(float2*)&g_y[row1 * DD + c] = w1;
    }
}

// ---------------------------------------------------------------------------
extern "C" void kernel_launch(void* const* d_in, const int* in_sizes, int n_in,
                              void* d_out, int out_size)
{
    const float* x    = (const float*)d_in[0];
    const float* bias = (const float*)d_in[1];
    const float* Wqkv = (const float*)d_in[2];
    const float* bqkv = (const float*)d_in[3];
    const float* Wo   = (const float*)d_in[4];
    const float* bo   = (const float*)d_in[5];
    float* out = (float*)d_out;

    const int gemm_smem = 6 * 4608 * 4;   // 110592
    const int attn_smem = 24576 * 4;      // 98304

    cudaFuncSetAttribute(hp_gemm_mma<true>,
                         cudaFuncAttributeMaxDynamicSharedMemorySize, gemm_smem);
    cudaFuncSetAttribute(hp_gemm_mma<false>,
                         cudaFuncAttributeMaxDynamicSharedMemorySize, gemm_smem);
    cudaFuncSetAttribute(hp_attn_mma,
                         cudaFuncAttributeMaxDynamicSharedMemorySize, attn_smem);

    float* gx;   cudaGetSymbolAddress((void**)&gx,   g_x);
    float* gwqT; cudaGetSymbolAddress((void**)&gwqT, g_wqT);
    float* gwoT; cudaGetSymbolAddress((void**)&gwoT, g_woT);
    float* gy;   cudaGetSymbolAddress((void**)&gy,   g_y);

    // Fork (R8 config): persistent bias transpose on side stream.
    cudaStream_t s1;
    cudaStreamCreateWithFlags(&s1, cudaStreamNonBlocking);
    cudaEvent_t eFork, eJoin;
    cudaEventCreateWithFlags(&eFork, cudaEventDisableTiming);
    cudaEventCreateWithFlags(&eJoin, cudaEventDisableTiming);

    cudaEventRecord(eFork, 0);
    cudaStreamWaitEvent(s1, eFork, 0);
    hp_bias_T<<<592, 256, 0, s1>>>(bias);
    cudaEventRecord(eJoin, s1);

    // main stream: round x; transpose+round weights; QKV GEMM
    hp_cvt4<<<BB*NN*DD/4/256, 256>>>((const float4*)x, (float4*)gx);
    hp_wT<<<dim3(48, 16), dim3(32, 8)>>>(Wqkv, gwqT, 512, 1536);
    hp_wT<<<dim3(16, 16), dim3(32, 8)>>>(Wo,   gwoT, 512, 512);
    hp_gemm_mma<true ><<<dim3(12, 64), 256, gemm_smem>>>(gx, gwqT, bqkv, nullptr);

    cudaStreamWaitEvent(0, eJoin, 0);
    hp_attn_mma<<<dim3(HH, NN / 128, BB), 256, attn_smem>>>();
    hp_gemm_mma<false><<<dim3(4, 64), 256, gemm_smem>>>(gy, gwoT, bo, out);

    cudaEventDestroy(eFork);
    cudaEventDestroy(eJoin);
    cudaStreamDestroy(s1);
}